// round 5
// baseline (speedup 1.0000x reference)
#include <cuda_runtime.h>
#include <cuda_bf16.h>
#include <math.h>

// ---------------- problem constants ----------------
#define DMODEL 768
#define NHEADS 12
#define DHEAD  64
#define DFF    3072
#define BBATCH 2
#define TSEQ   4096
#define MTOK   (BBATCH * TSEQ)   // 8192 tokens

// ---------------- scratch (device globals; no allocation allowed) ----------------
__device__ float g_Q  [MTOK * DMODEL];
__device__ float g_K  [MTOK * DMODEL];
__device__ float g_V  [MTOK * DMODEL];
__device__ float g_ATT[MTOK * DMODEL];
__device__ float g_R1 [MTOK * DMODEL];
__device__ float g_H  [MTOK * DMODEL];
__device__ float g_FF [MTOK * DFF];
__device__ float g_R2 [MTOK * DMODEL];

// =================================================================
// Generic fp32 GEMM: C[M,N] = A[M,K] @ W[K,N] + bias[N] (+res) (+relu)
// 128x128 tile, BK=16, 256 threads, 8x8 per thread.
// Requires M%128==0, N%128==0, K%16==0 (true for all our shapes).
// =================================================================
__global__ __launch_bounds__(256)
void gemm_kernel(const float* __restrict__ A, const float* __restrict__ W,
                 const float* __restrict__ bias, const float* __restrict__ res,
                 float* __restrict__ C, int M, int N, int K, int relu_flag)
{
    __shared__ float As[16][128];
    __shared__ float Ws[16][128];

    const int tid = threadIdx.x;
    const int bm  = blockIdx.y * 128;
    const int bn  = blockIdx.x * 128;
    const int tr  = tid >> 4;        // 0..15 -> rows tr*8..tr*8+7
    const int tc  = tid & 15;        // 0..15 -> cols tc*8..tc*8+7

    const int a_r = tid >> 2;        // 0..63
    const int a_c = (tid & 3) * 4;   // 0,4,8,12
    const int w_r = tid >> 5;        // 0..7
    const int w_c = (tid & 31) * 4;  // 0..124

    float acc[8][8];
#pragma unroll
    for (int i = 0; i < 8; i++)
#pragma unroll
        for (int j = 0; j < 8; j++) acc[i][j] = 0.f;

    const float* Ap = A + (size_t)bm * K;
    const float* Wp = W + bn;

    for (int k0 = 0; k0 < K; k0 += 16) {
        // load A tile 128x16 (transposed into As[k][m])
#pragma unroll
        for (int t = 0; t < 2; t++) {
            int r = a_r + t * 64;
            float4 v = *(const float4*)&Ap[(size_t)r * K + k0 + a_c];
            As[a_c + 0][r] = v.x;
            As[a_c + 1][r] = v.y;
            As[a_c + 2][r] = v.z;
            As[a_c + 3][r] = v.w;
        }
        // load W tile 16x128
#pragma unroll
        for (int t = 0; t < 2; t++) {
            int r = w_r + t * 8;
            float4 v = *(const float4*)&Wp[(size_t)(k0 + r) * N + w_c];
            *(float4*)&Ws[r][w_c] = v;
        }
        __syncthreads();

#pragma unroll
        for (int kk = 0; kk < 16; kk++) {
            float a[8], b[8];
            *(float4*)&a[0] = *(const float4*)&As[kk][tr * 8];
            *(float4*)&a[4] = *(const float4*)&As[kk][tr * 8 + 4];
            *(float4*)&b[0] = *(const float4*)&Ws[kk][tc * 8];
            *(float4*)&b[4] = *(const float4*)&Ws[kk][tc * 8 + 4];
#pragma unroll
            for (int i = 0; i < 8; i++)
#pragma unroll
                for (int j = 0; j < 8; j++)
                    acc[i][j] += a[i] * b[j];
        }
        __syncthreads();
    }

    // epilogue
#pragma unroll
    for (int i = 0; i < 8; i++) {
        int row = bm + tr * 8 + i;
        size_t base = (size_t)row * N + bn + tc * 8;
#pragma unroll
        for (int jv = 0; jv < 2; jv++) {
            float4 bv = *(const float4*)&bias[bn + tc * 8 + jv * 4];
            float4 o;
            o.x = acc[i][jv * 4 + 0] + bv.x;
            o.y = acc[i][jv * 4 + 1] + bv.y;
            o.z = acc[i][jv * 4 + 2] + bv.z;
            o.w = acc[i][jv * 4 + 3] + bv.w;
            if (res) {
                float4 rv = *(const float4*)&res[base + jv * 4];
                o.x += rv.x; o.y += rv.y; o.z += rv.z; o.w += rv.w;
            }
            if (relu_flag) {
                o.x = fmaxf(o.x, 0.f); o.y = fmaxf(o.y, 0.f);
                o.z = fmaxf(o.z, 0.f); o.w = fmaxf(o.w, 0.f);
            }
            *(float4*)&C[base + jv * 4] = o;
        }
    }
}

// =================================================================
// Flash attention (causal), fp32. One block = one (b, h, 64-query tile).
// 256 threads; each thread owns a 4x4 patch of the 64x64 S tile and a
// 4x4 patch of the 64x64 O tile. Streaming softmax over 64-key chunks.
// Layouts: Q/K/V are [MTOK, 768], head slice = 64 contiguous floats.
// =================================================================
#define QP 68   // Qs/Vs/Ps pitch (floats) - keeps float4 alignment, breaks bank patterns
#define KP 65   // K-transposed pitch
#define ATT_SMEM (3 * 64 * QP * 4)   // Qs + (Kt/Ps shared) + Vs, bytes

__global__ __launch_bounds__(256)
void attn_kernel(const float* __restrict__ Qg, const float* __restrict__ Kg,
                 const float* __restrict__ Vg, float* __restrict__ Og)
{
    extern __shared__ float sm[];
    float* Qs  = sm;                 // [64][QP]
    float* KtP = sm + 64 * QP;       // K transposed [64 d][KP] ; reused as P [64][QP]
    float* Vs  = sm + 2 * 64 * QP;   // [64][QP]

    const int q0 = blockIdx.x * 64;
    const int h  = blockIdx.y;
    const int b  = blockIdx.z;
    const int tid = threadIdx.x;
    const int tr = tid >> 4;            // row group 0..15
    const int tc = tid & 15;            // col group 0..15
    const int rbase = tr * 4;
    const int cbase = tc * 4;
    const float scale = 0.125f;         // 1/sqrt(64)

    // load Q tile (scaled)
    for (int i = tid; i < 64 * 16; i += 256) {
        int r  = i >> 4;
        int cv = (i & 15) * 4;
        float4 v = *(const float4*)&Qg[((size_t)(b * TSEQ + q0 + r)) * DMODEL + h * DHEAD + cv];
        float* d = &Qs[r * QP + cv];
        d[0] = v.x * scale; d[1] = v.y * scale; d[2] = v.z * scale; d[3] = v.w * scale;
    }

    float m_[4], l_[4], o_[4][4];
#pragma unroll
    for (int i = 0; i < 4; i++) {
        m_[i] = -1e30f; l_[i] = 0.f;
#pragma unroll
        for (int j = 0; j < 4; j++) o_[i][j] = 0.f;
    }

    for (int j0 = 0; j0 <= q0; j0 += 64) {
        __syncthreads();   // protect Kt/Ps/Vs from previous iteration readers

        // load K (transposed into [d][key]) and V (natural [key][d])
        for (int i = tid; i < 64 * 16; i += 256) {
            int r  = i >> 4;
            int cv = (i & 15) * 4;
            size_t g = ((size_t)(b * TSEQ + j0 + r)) * DMODEL + h * DHEAD + cv;
            float4 kv = *(const float4*)&Kg[g];
            KtP[(cv + 0) * KP + r] = kv.x;
            KtP[(cv + 1) * KP + r] = kv.y;
            KtP[(cv + 2) * KP + r] = kv.z;
            KtP[(cv + 3) * KP + r] = kv.w;
            float4 vv = *(const float4*)&Vg[g];
            *(float4*)&Vs[r * QP + cv] = vv;
        }
        __syncthreads();

        // S = Q K^T (scaled)
        float s[4][4];
#pragma unroll
        for (int i = 0; i < 4; i++)
#pragma unroll
            for (int j = 0; j < 4; j++) s[i][j] = 0.f;

#pragma unroll 8
        for (int kk = 0; kk < 64; kk++) {
            float a0 = Qs[(rbase + 0) * QP + kk];
            float a1 = Qs[(rbase + 1) * QP + kk];
            float a2 = Qs[(rbase + 2) * QP + kk];
            float a3 = Qs[(rbase + 3) * QP + kk];
            float b0 = KtP[kk * KP + cbase + 0];
            float b1 = KtP[kk * KP + cbase + 1];
            float b2 = KtP[kk * KP + cbase + 2];
            float b3 = KtP[kk * KP + cbase + 3];
            s[0][0] += a0 * b0; s[0][1] += a0 * b1; s[0][2] += a0 * b2; s[0][3] += a0 * b3;
            s[1][0] += a1 * b0; s[1][1] += a1 * b1; s[1][2] += a1 * b2; s[1][3] += a1 * b3;
            s[2][0] += a2 * b0; s[2][1] += a2 * b1; s[2][2] += a2 * b2; s[2][3] += a2 * b3;
            s[3][0] += a3 * b0; s[3][1] += a3 * b1; s[3][2] += a3 * b2; s[3][3] += a3 * b3;
        }

        // causal mask (only needed on the diagonal chunk)
        if (j0 == q0) {
#pragma unroll
            for (int i = 0; i < 4; i++)
#pragma unroll
                for (int j = 0; j < 4; j++)
                    if (j0 + cbase + j > q0 + rbase + i) s[i][j] = -1e30f;
        }

        // streaming softmax update (row groups of 16 lanes: same tr)
#pragma unroll
        for (int i = 0; i < 4; i++) {
            float cm = fmaxf(fmaxf(s[i][0], s[i][1]), fmaxf(s[i][2], s[i][3]));
#pragma unroll
            for (int off = 8; off; off >>= 1)
                cm = fmaxf(cm, __shfl_xor_sync(0xffffffffu, cm, off));
            float mn = fmaxf(m_[i], cm);
            float corr = __expf(m_[i] - mn);
            m_[i] = mn;
            float rs = 0.f;
#pragma unroll
            for (int j = 0; j < 4; j++) {
                float p = __expf(s[i][j] - mn);
                s[i][j] = p;
                rs += p;
            }
#pragma unroll
            for (int off = 8; off; off >>= 1)
                rs += __shfl_xor_sync(0xffffffffu, rs, off);
            l_[i] = l_[i] * corr + rs;
#pragma unroll
            for (int j = 0; j < 4; j++) o_[i][j] *= corr;
        }

        __syncthreads();   // everyone is done reading KtP as K
        // write P into the KtP buffer (now used as Ps[64][QP])
#pragma unroll
        for (int i = 0; i < 4; i++) {
            float4 p4 = make_float4(s[i][0], s[i][1], s[i][2], s[i][3]);
            *(float4*)&KtP[(rbase + i) * QP + cbase] = p4;
        }
        __syncthreads();

        // O += P @ V
#pragma unroll 8
        for (int kk = 0; kk < 64; kk++) {
            float p0 = KtP[(rbase + 0) * QP + kk];
            float p1 = KtP[(rbase + 1) * QP + kk];
            float p2 = KtP[(rbase + 2) * QP + kk];
            float p3 = KtP[(rbase + 3) * QP + kk];
            float4 v4 = *(const float4*)&Vs[kk * QP + cbase];
            o_[0][0] += p0 * v4.x; o_[0][1] += p0 * v4.y; o_[0][2] += p0 * v4.z; o_[0][3] += p0 * v4.w;
            o_[1][0] += p1 * v4.x; o_[1][1] += p1 * v4.y; o_[1][2] += p1 * v4.z; o_[1][3] += p1 * v4.w;
            o_[2][0] += p2 * v4.x; o_[2][1] += p2 * v4.y; o_[2][2] += p2 * v4.z; o_[2][3] += p2 * v4.w;
            o_[3][0] += p3 * v4.x; o_[3][1] += p3 * v4.y; o_[3][2] += p3 * v4.z; o_[3][3] += p3 * v4.w;
        }
    }

    // final normalize + write (merge heads: [MTOK, 768])
#pragma unroll
    for (int i = 0; i < 4; i++) {
        float invl = 1.f / l_[i];
        int q = q0 + rbase + i;
        size_t base = ((size_t)(b * TSEQ + q)) * DMODEL + h * DHEAD + cbase;
        float4 o4 = make_float4(o_[i][0] * invl, o_[i][1] * invl,
                                o_[i][2] * invl, o_[i][3] * invl);
        *(float4*)&Og[base] = o4;
    }
}

// =================================================================
// LayerNorm over last dim (768). One block (256 threads) per row.
// =================================================================
__global__ __launch_bounds__(256)
void ln_kernel(const float* __restrict__ in, const float* __restrict__ g,
               const float* __restrict__ be, float* __restrict__ out)
{
    const int row = blockIdx.x;
    const int tid = threadIdx.x;
    const float* xr = in + (size_t)row * DMODEL;

    float v0 = xr[tid];
    float v1 = xr[tid + 256];
    float v2 = xr[tid + 512];
    float s  = v0 + v1 + v2;
    float s2 = v0 * v0 + v1 * v1 + v2 * v2;

    __shared__ float rs[8], rs2[8], stats[2];
#pragma unroll
    for (int off = 16; off; off >>= 1) {
        s  += __shfl_xor_sync(0xffffffffu, s,  off);
        s2 += __shfl_xor_sync(0xffffffffu, s2, off);
    }
    int w = tid >> 5, lane = tid & 31;
    if (lane == 0) { rs[w] = s; rs2[w] = s2; }
    __syncthreads();
    if (tid == 0) {
        float S = 0.f, S2 = 0.f;
#pragma unroll
        for (int i = 0; i < 8; i++) { S += rs[i]; S2 += rs2[i]; }
        float mean = S * (1.f / DMODEL);
        float var  = S2 * (1.f / DMODEL) - mean * mean;
        stats[0] = mean;
        stats[1] = rsqrtf(var + 1e-5f);
    }
    __syncthreads();
    float mean = stats[0], r = stats[1];
    float* orow = out + (size_t)row * DMODEL;
    orow[tid]       = (v0 - mean) * r * g[tid]       + be[tid];
    orow[tid + 256] = (v1 - mean) * r * g[tid + 256] + be[tid + 256];
    orow[tid + 512] = (v2 - mean) * r * g[tid + 512] + be[tid + 512];
}

// =================================================================
// Host launch
// =================================================================
extern "C" void kernel_launch(void* const* d_in, const int* in_sizes, int n_in,
                              void* d_out, int out_size)
{
    const float* x  = (const float*)d_in[0];
    const float* wq = (const float*)d_in[1];
    const float* bq = (const float*)d_in[2];
    const float* wk = (const float*)d_in[3];
    const float* bk = (const float*)d_in[4];
    const float* wv = (const float*)d_in[5];
    const float* bv = (const float*)d_in[6];
    const float* wo = (const float*)d_in[7];
    const float* bo = (const float*)d_in[8];
    const float* w1 = (const float*)d_in[9];
    const float* b1 = (const float*)d_in[10];
    const float* w2 = (const float*)d_in[11];
    const float* b2 = (const float*)d_in[12];
    const float* g1 = (const float*)d_in[13];
    const float* be1= (const float*)d_in[14];
    const float* g2 = (const float*)d_in[15];
    const float* be2= (const float*)d_in[16];
    float* out = (float*)d_out;

    float *Q, *K, *V, *ATT, *R1, *H, *FF, *R2;
    cudaGetSymbolAddress((void**)&Q,   g_Q);
    cudaGetSymbolAddress((void**)&K,   g_K);
    cudaGetSymbolAddress((void**)&V,   g_V);
    cudaGetSymbolAddress((void**)&ATT, g_ATT);
    cudaGetSymbolAddress((void**)&R1,  g_R1);
    cudaGetSymbolAddress((void**)&H,   g_H);
    cudaGetSymbolAddress((void**)&FF,  g_FF);
    cudaGetSymbolAddress((void**)&R2,  g_R2);

    cudaFuncSetAttribute(attn_kernel, cudaFuncAttributeMaxDynamicSharedMemorySize, ATT_SMEM);

    dim3 gD(DMODEL / 128, MTOK / 128);   // (6, 64)
    dim3 gF(DFF / 128,    MTOK / 128);   // (24, 64)

    // QKV projections
    gemm_kernel<<<gD, 256>>>(x, wq, bq, nullptr, Q, MTOK, DMODEL, DMODEL, 0);
    gemm_kernel<<<gD, 256>>>(x, wk, bk, nullptr, K, MTOK, DMODEL, DMODEL, 0);
    gemm_kernel<<<gD, 256>>>(x, wv, bv, nullptr, V, MTOK, DMODEL, DMODEL, 0);

    // causal flash attention
    attn_kernel<<<dim3(TSEQ / 64, NHEADS, BBATCH), 256, ATT_SMEM>>>(Q, K, V, ATT);

    // output projection + residual, LN1
    gemm_kernel<<<gD, 256>>>(ATT, wo, bo, x, R1, MTOK, DMODEL, DMODEL, 0);
    ln_kernel<<<MTOK, 256>>>(R1, g1, be1, H);

    // FFN
    gemm_kernel<<<gF, 256>>>(H, w1, b1, nullptr, FF, MTOK, DFF, DMODEL, 1);
    gemm_kernel<<<gD, 256>>>(FF, w2, b2, H, R2, MTOK, DMODEL, DFF, 0);

    // LN2 -> output
    ln_kernel<<<MTOK, 256>>>(R2, g2, be2, out);
}

// round 6
// speedup vs baseline: 1.0032x; 1.0032x over previous
#include <cuda_runtime.h>
#include <cuda_bf16.h>
#include <math.h>

// ---------------- problem constants ----------------
#define DMODEL 768
#define NHEADS 12
#define DHEAD  64
#define DFF    3072
#define BBATCH 2
#define TSEQ   4096
#define MTOK   (BBATCH * TSEQ)   // 8192 tokens

// ---------------- scratch (device globals; no allocation allowed) ----------------
__device__ float g_Q  [MTOK * DMODEL];
__device__ float g_K  [MTOK * DMODEL];
__device__ float g_V  [MTOK * DMODEL];
__device__ float g_ATT[MTOK * DMODEL];
__device__ float g_R1 [MTOK * DMODEL];
__device__ float g_H  [MTOK * DMODEL];
__device__ float g_FF [MTOK * DFF];
__device__ float g_R2 [MTOK * DMODEL];

// =================================================================
// Generic fp32 GEMM: C[M,N] = A[M,K] @ W[K,N] + bias[N] (+res) (+relu)
// 128x128 tile, BK=16, 256 threads, 8x8 per thread.
// Requires M%128==0, N%128==0, K%16==0 (true for all our shapes).
// =================================================================
__global__ __launch_bounds__(256)
void gemm_kernel(const float* __restrict__ A, const float* __restrict__ W,
                 const float* __restrict__ bias, const float* __restrict__ res,
                 float* __restrict__ C, int M, int N, int K, int relu_flag)
{
    __shared__ float As[16][128];
    __shared__ float Ws[16][128];

    const int tid = threadIdx.x;
    const int bm  = blockIdx.y * 128;
    const int bn  = blockIdx.x * 128;
    const int tr  = tid >> 4;        // 0..15 -> rows tr*8..tr*8+7
    const int tc  = tid & 15;        // 0..15 -> cols tc*8..tc*8+7

    const int a_r = tid >> 2;        // 0..63
    const int a_c = (tid & 3) * 4;   // 0,4,8,12
    const int w_r = tid >> 5;        // 0..7
    const int w_c = (tid & 31) * 4;  // 0..124

    float acc[8][8];
#pragma unroll
    for (int i = 0; i < 8; i++)
#pragma unroll
        for (int j = 0; j < 8; j++) acc[i][j] = 0.f;

    const float* Ap = A + (size_t)bm * K;
    const float* Wp = W + bn;

    for (int k0 = 0; k0 < K; k0 += 16) {
        // load A tile 128x16 (transposed into As[k][m])
#pragma unroll
        for (int t = 0; t < 2; t++) {
            int r = a_r + t * 64;
            float4 v = *(const float4*)&Ap[(size_t)r * K + k0 + a_c];
            As[a_c + 0][r] = v.x;
            As[a_c + 1][r] = v.y;
            As[a_c + 2][r] = v.z;
            As[a_c + 3][r] = v.w;
        }
        // load W tile 16x128
#pragma unroll
        for (int t = 0; t < 2; t++) {
            int r = w_r + t * 8;
            float4 v = *(const float4*)&Wp[(size_t)(k0 + r) * N + w_c];
            *(float4*)&Ws[r][w_c] = v;
        }
        __syncthreads();

#pragma unroll
        for (int kk = 0; kk < 16; kk++) {
            float a[8], b[8];
            *(float4*)&a[0] = *(const float4*)&As[kk][tr * 8];
            *(float4*)&a[4] = *(const float4*)&As[kk][tr * 8 + 4];
            *(float4*)&b[0] = *(const float4*)&Ws[kk][tc * 8];
            *(float4*)&b[4] = *(const float4*)&Ws[kk][tc * 8 + 4];
#pragma unroll
            for (int i = 0; i < 8; i++)
#pragma unroll
                for (int j = 0; j < 8; j++)
                    acc[i][j] += a[i] * b[j];
        }
        __syncthreads();
    }

    // epilogue
#pragma unroll
    for (int i = 0; i < 8; i++) {
        int row = bm + tr * 8 + i;
        size_t base = (size_t)row * N + bn + tc * 8;
#pragma unroll
        for (int jv = 0; jv < 2; jv++) {
            float4 bv = *(const float4*)&bias[bn + tc * 8 + jv * 4];
            float4 o;
            o.x = acc[i][jv * 4 + 0] + bv.x;
            o.y = acc[i][jv * 4 + 1] + bv.y;
            o.z = acc[i][jv * 4 + 2] + bv.z;
            o.w = acc[i][jv * 4 + 3] + bv.w;
            if (res) {
                float4 rv = *(const float4*)&res[base + jv * 4];
                o.x += rv.x; o.y += rv.y; o.z += rv.z; o.w += rv.w;
            }
            if (relu_flag) {
                o.x = fmaxf(o.x, 0.f); o.y = fmaxf(o.y, 0.f);
                o.z = fmaxf(o.z, 0.f); o.w = fmaxf(o.w, 0.f);
            }
            *(float4*)&C[base + jv * 4] = o;
        }
    }
}

// =================================================================
// Flash attention (causal), fp32. One block = one (b, h, 64-query tile).
// 256 threads; each thread owns a 4x4 patch of the 64x64 S tile and a
// 4x4 patch of the 64x64 O tile. Streaming softmax over 64-key chunks.
// Layouts: Q/K/V are [MTOK, 768], head slice = 64 contiguous floats.
// =================================================================
#define QP 68   // Qs/Vs/Ps pitch (floats) - keeps float4 alignment, breaks bank patterns
#define KP 65   // K-transposed pitch
#define ATT_SMEM (3 * 64 * QP * 4)   // Qs + (Kt/Ps shared) + Vs, bytes

__global__ __launch_bounds__(256)
void attn_kernel(const float* __restrict__ Qg, const float* __restrict__ Kg,
                 const float* __restrict__ Vg, float* __restrict__ Og)
{
    extern __shared__ float sm[];
    float* Qs  = sm;                 // [64][QP]
    float* KtP = sm + 64 * QP;       // K transposed [64 d][KP] ; reused as P [64][QP]
    float* Vs  = sm + 2 * 64 * QP;   // [64][QP]

    const int q0 = blockIdx.x * 64;
    const int h  = blockIdx.y;
    const int b  = blockIdx.z;
    const int tid = threadIdx.x;
    const int tr = tid >> 4;            // row group 0..15
    const int tc = tid & 15;            // col group 0..15
    const int rbase = tr * 4;
    const int cbase = tc * 4;
    const float scale = 0.125f;         // 1/sqrt(64)

    // load Q tile (scaled)
    for (int i = tid; i < 64 * 16; i += 256) {
        int r  = i >> 4;
        int cv = (i & 15) * 4;
        float4 v = *(const float4*)&Qg[((size_t)(b * TSEQ + q0 + r)) * DMODEL + h * DHEAD + cv];
        float* d = &Qs[r * QP + cv];
        d[0] = v.x * scale; d[1] = v.y * scale; d[2] = v.z * scale; d[3] = v.w * scale;
    }

    float m_[4], l_[4], o_[4][4];
#pragma unroll
    for (int i = 0; i < 4; i++) {
        m_[i] = -1e30f; l_[i] = 0.f;
#pragma unroll
        for (int j = 0; j < 4; j++) o_[i][j] = 0.f;
    }

    for (int j0 = 0; j0 <= q0; j0 += 64) {
        __syncthreads();   // protect Kt/Ps/Vs from previous iteration readers

        // load K (transposed into [d][key]) and V (natural [key][d])
        for (int i = tid; i < 64 * 16; i += 256) {
            int r  = i >> 4;
            int cv = (i & 15) * 4;
            size_t g = ((size_t)(b * TSEQ + j0 + r)) * DMODEL + h * DHEAD + cv;
            float4 kv = *(const float4*)&Kg[g];
            KtP[(cv + 0) * KP + r] = kv.x;
            KtP[(cv + 1) * KP + r] = kv.y;
            KtP[(cv + 2) * KP + r] = kv.z;
            KtP[(cv + 3) * KP + r] = kv.w;
            float4 vv = *(const float4*)&Vg[g];
            *(float4*)&Vs[r * QP + cv] = vv;
        }
        __syncthreads();

        // S = Q K^T (scaled)
        float s[4][4];
#pragma unroll
        for (int i = 0; i < 4; i++)
#pragma unroll
            for (int j = 0; j < 4; j++) s[i][j] = 0.f;

#pragma unroll 8
        for (int kk = 0; kk < 64; kk++) {
            float a0 = Qs[(rbase + 0) * QP + kk];
            float a1 = Qs[(rbase + 1) * QP + kk];
            float a2 = Qs[(rbase + 2) * QP + kk];
            float a3 = Qs[(rbase + 3) * QP + kk];
            float b0 = KtP[kk * KP + cbase + 0];
            float b1 = KtP[kk * KP + cbase + 1];
            float b2 = KtP[kk * KP + cbase + 2];
            float b3 = KtP[kk * KP + cbase + 3];
            s[0][0] += a0 * b0; s[0][1] += a0 * b1; s[0][2] += a0 * b2; s[0][3] += a0 * b3;
            s[1][0] += a1 * b0; s[1][1] += a1 * b1; s[1][2] += a1 * b2; s[1][3] += a1 * b3;
            s[2][0] += a2 * b0; s[2][1] += a2 * b1; s[2][2] += a2 * b2; s[2][3] += a2 * b3;
            s[3][0] += a3 * b0; s[3][1] += a3 * b1; s[3][2] += a3 * b2; s[3][3] += a3 * b3;
        }

        // causal mask (only needed on the diagonal chunk)
        if (j0 == q0) {
#pragma unroll
            for (int i = 0; i < 4; i++)
#pragma unroll
                for (int j = 0; j < 4; j++)
                    if (j0 + cbase + j > q0 + rbase + i) s[i][j] = -1e30f;
        }

        // streaming softmax update (row groups of 16 lanes: same tr)
#pragma unroll
        for (int i = 0; i < 4; i++) {
            float cm = fmaxf(fmaxf(s[i][0], s[i][1]), fmaxf(s[i][2], s[i][3]));
#pragma unroll
            for (int off = 8; off; off >>= 1)
                cm = fmaxf(cm, __shfl_xor_sync(0xffffffffu, cm, off));
            float mn = fmaxf(m_[i], cm);
            float corr = __expf(m_[i] - mn);
            m_[i] = mn;
            float rs = 0.f;
#pragma unroll
            for (int j = 0; j < 4; j++) {
                float p = __expf(s[i][j] - mn);
                s[i][j] = p;
                rs += p;
            }
#pragma unroll
            for (int off = 8; off; off >>= 1)
                rs += __shfl_xor_sync(0xffffffffu, rs, off);
            l_[i] = l_[i] * corr + rs;
#pragma unroll
            for (int j = 0; j < 4; j++) o_[i][j] *= corr;
        }

        __syncthreads();   // everyone is done reading KtP as K
        // write P into the KtP buffer (now used as Ps[64][QP])
#pragma unroll
        for (int i = 0; i < 4; i++) {
            float4 p4 = make_float4(s[i][0], s[i][1], s[i][2], s[i][3]);
            *(float4*)&KtP[(rbase + i) * QP + cbase] = p4;
        }
        __syncthreads();

        // O += P @ V
#pragma unroll 8
        for (int kk = 0; kk < 64; kk++) {
            float p0 = KtP[(rbase + 0) * QP + kk];
            float p1 = KtP[(rbase + 1) * QP + kk];
            float p2 = KtP[(rbase + 2) * QP + kk];
            float p3 = KtP[(rbase + 3) * QP + kk];
            float4 v4 = *(const float4*)&Vs[kk * QP + cbase];
            o_[0][0] += p0 * v4.x; o_[0][1] += p0 * v4.y; o_[0][2] += p0 * v4.z; o_[0][3] += p0 * v4.w;
            o_[1][0] += p1 * v4.x; o_[1][1] += p1 * v4.y; o_[1][2] += p1 * v4.z; o_[1][3] += p1 * v4.w;
            o_[2][0] += p2 * v4.x; o_[2][1] += p2 * v4.y; o_[2][2] += p2 * v4.z; o_[2][3] += p2 * v4.w;
            o_[3][0] += p3 * v4.x; o_[3][1] += p3 * v4.y; o_[3][2] += p3 * v4.z; o_[3][3] += p3 * v4.w;
        }
    }

    // final normalize + write (merge heads: [MTOK, 768])
#pragma unroll
    for (int i = 0; i < 4; i++) {
        float invl = 1.f / l_[i];
        int q = q0 + rbase + i;
        size_t base = ((size_t)(b * TSEQ + q)) * DMODEL + h * DHEAD + cbase;
        float4 o4 = make_float4(o_[i][0] * invl, o_[i][1] * invl,
                                o_[i][2] * invl, o_[i][3] * invl);
        *(float4*)&Og[base] = o4;
    }
}

// =================================================================
// LayerNorm over last dim (768). One block (256 threads) per row.
// =================================================================
__global__ __launch_bounds__(256)
void ln_kernel(const float* __restrict__ in, const float* __restrict__ g,
               const float* __restrict__ be, float* __restrict__ out)
{
    const int row = blockIdx.x;
    const int tid = threadIdx.x;
    const float* xr = in + (size_t)row * DMODEL;

    float v0 = xr[tid];
    float v1 = xr[tid + 256];
    float v2 = xr[tid + 512];
    float s  = v0 + v1 + v2;
    float s2 = v0 * v0 + v1 * v1 + v2 * v2;

    __shared__ float rs[8], rs2[8], stats[2];
#pragma unroll
    for (int off = 16; off; off >>= 1) {
        s  += __shfl_xor_sync(0xffffffffu, s,  off);
        s2 += __shfl_xor_sync(0xffffffffu, s2, off);
    }
    int w = tid >> 5, lane = tid & 31;
    if (lane == 0) { rs[w] = s; rs2[w] = s2; }
    __syncthreads();
    if (tid == 0) {
        float S = 0.f, S2 = 0.f;
#pragma unroll
        for (int i = 0; i < 8; i++) { S += rs[i]; S2 += rs2[i]; }
        float mean = S * (1.f / DMODEL);
        float var  = S2 * (1.f / DMODEL) - mean * mean;
        stats[0] = mean;
        stats[1] = rsqrtf(var + 1e-5f);
    }
    __syncthreads();
    float mean = stats[0], r = stats[1];
    float* orow = out + (size_t)row * DMODEL;
    orow[tid]       = (v0 - mean) * r * g[tid]       + be[tid];
    orow[tid + 256] = (v1 - mean) * r * g[tid + 256] + be[tid + 256];
    orow[tid + 512] = (v2 - mean) * r * g[tid + 512] + be[tid + 512];
}

// =================================================================
// Host launch
// =================================================================
extern "C" void kernel_launch(void* const* d_in, const int* in_sizes, int n_in,
                              void* d_out, int out_size)
{
    const float* x  = (const float*)d_in[0];
    const float* wq = (const float*)d_in[1];
    const float* bq = (const float*)d_in[2];
    const float* wk = (const float*)d_in[3];
    const float* bk = (const float*)d_in[4];
    const float* wv = (const float*)d_in[5];
    const float* bv = (const float*)d_in[6];
    const float* wo = (const float*)d_in[7];
    const float* bo = (const float*)d_in[8];
    const float* w1 = (const float*)d_in[9];
    const float* b1 = (const float*)d_in[10];
    const float* w2 = (const float*)d_in[11];
    const float* b2 = (const float*)d_in[12];
    const float* g1 = (const float*)d_in[13];
    const float* be1= (const float*)d_in[14];
    const float* g2 = (const float*)d_in[15];
    const float* be2= (const float*)d_in[16];
    float* out = (float*)d_out;

    float *Q, *K, *V, *ATT, *R1, *H, *FF, *R2;
    cudaGetSymbolAddress((void**)&Q,   g_Q);
    cudaGetSymbolAddress((void**)&K,   g_K);
    cudaGetSymbolAddress((void**)&V,   g_V);
    cudaGetSymbolAddress((void**)&ATT, g_ATT);
    cudaGetSymbolAddress((void**)&R1,  g_R1);
    cudaGetSymbolAddress((void**)&H,   g_H);
    cudaGetSymbolAddress((void**)&FF,  g_FF);
    cudaGetSymbolAddress((void**)&R2,  g_R2);

    cudaFuncSetAttribute(attn_kernel, cudaFuncAttributeMaxDynamicSharedMemorySize, ATT_SMEM);

    dim3 gD(DMODEL / 128, MTOK / 128);   // (6, 64)
    dim3 gF(DFF / 128,    MTOK / 128);   // (24, 64)

    // QKV projections
    gemm_kernel<<<gD, 256>>>(x, wq, bq, nullptr, Q, MTOK, DMODEL, DMODEL, 0);
    gemm_kernel<<<gD, 256>>>(x, wk, bk, nullptr, K, MTOK, DMODEL, DMODEL, 0);
    gemm_kernel<<<gD, 256>>>(x, wv, bv, nullptr, V, MTOK, DMODEL, DMODEL, 0);

    // causal flash attention
    attn_kernel<<<dim3(TSEQ / 64, NHEADS, BBATCH), 256, ATT_SMEM>>>(Q, K, V, ATT);

    // output projection + residual, LN1
    gemm_kernel<<<gD, 256>>>(ATT, wo, bo, x, R1, MTOK, DMODEL, DMODEL, 0);
    ln_kernel<<<MTOK, 256>>>(R1, g1, be1, H);

    // FFN
    gemm_kernel<<<gF, 256>>>(H, w1, b1, nullptr, FF, MTOK, DFF, DMODEL, 1);
    gemm_kernel<<<gD, 256>>>(FF, w2, b2, H, R2, MTOK, DMODEL, DFF, 0);

    // LN2 -> output
    ln_kernel<<<MTOK, 256>>>(R2, g2, be2, out);
}

// round 7
// speedup vs baseline: 1.0076x; 1.0044x over previous
#include <cuda_runtime.h>
#include <cuda_bf16.h>
#include <math.h>

// ---------------- problem constants ----------------
#define DMODEL 768
#define NHEADS 12
#define DHEAD  64
#define DFF    3072
#define BBATCH 2
#define TSEQ   4096
#define MTOK   (BBATCH * TSEQ)   // 8192 tokens

// ---------------- scratch (device globals; no allocation allowed) ----------------
__device__ float g_Q  [MTOK * DMODEL];
__device__ float g_K  [MTOK * DMODEL];
__device__ float g_V  [MTOK * DMODEL];
__device__ float g_ATT[MTOK * DMODEL];
__device__ float g_R1 [MTOK * DMODEL];
__device__ float g_H  [MTOK * DMODEL];
__device__ float g_FF [MTOK * DFF];
__device__ float g_R2 [MTOK * DMODEL];

// =================================================================
// Generic fp32 GEMM: C[M,N] = A[M,K] @ W[K,N] + bias[N] (+res) (+relu)
// 128x128 tile, BK=16, 256 threads, 8x8 per thread.
// Requires M%128==0, N%128==0, K%16==0 (true for all our shapes).
// =================================================================
__global__ __launch_bounds__(256)
void gemm_kernel(const float* __restrict__ A, const float* __restrict__ W,
                 const float* __restrict__ bias, const float* __restrict__ res,
                 float* __restrict__ C, int M, int N, int K, int relu_flag)
{
    __shared__ float As[16][128];
    __shared__ float Ws[16][128];

    const int tid = threadIdx.x;
    const int bm  = blockIdx.y * 128;
    const int bn  = blockIdx.x * 128;
    const int tr  = tid >> 4;        // 0..15 -> rows tr*8..tr*8+7
    const int tc  = tid & 15;        // 0..15 -> cols tc*8..tc*8+7

    const int a_r = tid >> 2;        // 0..63
    const int a_c = (tid & 3) * 4;   // 0,4,8,12
    const int w_r = tid >> 5;        // 0..7
    const int w_c = (tid & 31) * 4;  // 0..124

    float acc[8][8];
#pragma unroll
    for (int i = 0; i < 8; i++)
#pragma unroll
        for (int j = 0; j < 8; j++) acc[i][j] = 0.f;

    const float* Ap = A + (size_t)bm * K;
    const float* Wp = W + bn;

    for (int k0 = 0; k0 < K; k0 += 16) {
        // load A tile 128x16 (transposed into As[k][m])
#pragma unroll
        for (int t = 0; t < 2; t++) {
            int r = a_r + t * 64;
            float4 v = *(const float4*)&Ap[(size_t)r * K + k0 + a_c];
            As[a_c + 0][r] = v.x;
            As[a_c + 1][r] = v.y;
            As[a_c + 2][r] = v.z;
            As[a_c + 3][r] = v.w;
        }
        // load W tile 16x128
#pragma unroll
        for (int t = 0; t < 2; t++) {
            int r = w_r + t * 8;
            float4 v = *(const float4*)&Wp[(size_t)(k0 + r) * N + w_c];
            *(float4*)&Ws[r][w_c] = v;
        }
        __syncthreads();

#pragma unroll
        for (int kk = 0; kk < 16; kk++) {
            float a[8], b[8];
            *(float4*)&a[0] = *(const float4*)&As[kk][tr * 8];
            *(float4*)&a[4] = *(const float4*)&As[kk][tr * 8 + 4];
            *(float4*)&b[0] = *(const float4*)&Ws[kk][tc * 8];
            *(float4*)&b[4] = *(const float4*)&Ws[kk][tc * 8 + 4];
#pragma unroll
            for (int i = 0; i < 8; i++)
#pragma unroll
                for (int j = 0; j < 8; j++)
                    acc[i][j] += a[i] * b[j];
        }
        __syncthreads();
    }

    // epilogue
#pragma unroll
    for (int i = 0; i < 8; i++) {
        int row = bm + tr * 8 + i;
        size_t base = (size_t)row * N + bn + tc * 8;
#pragma unroll
        for (int jv = 0; jv < 2; jv++) {
            float4 bv = *(const float4*)&bias[bn + tc * 8 + jv * 4];
            float4 o;
            o.x = acc[i][jv * 4 + 0] + bv.x;
            o.y = acc[i][jv * 4 + 1] + bv.y;
            o.z = acc[i][jv * 4 + 2] + bv.z;
            o.w = acc[i][jv * 4 + 3] + bv.w;
            if (res) {
                float4 rv = *(const float4*)&res[base + jv * 4];
                o.x += rv.x; o.y += rv.y; o.z += rv.z; o.w += rv.w;
            }
            if (relu_flag) {
                o.x = fmaxf(o.x, 0.f); o.y = fmaxf(o.y, 0.f);
                o.z = fmaxf(o.z, 0.f); o.w = fmaxf(o.w, 0.f);
            }
            *(float4*)&C[base + jv * 4] = o;
        }
    }
}

// =================================================================
// Flash attention (causal), fp32. One block = one (b, h, 64-query tile).
// 256 threads; each thread owns a 4x4 patch of the 64x64 S tile and a
// 4x4 patch of the 64x64 O tile. Streaming softmax over 64-key chunks.
// Layouts: Q/K/V are [MTOK, 768], head slice = 64 contiguous floats.
// =================================================================
#define QP 68   // Qs/Vs/Ps pitch (floats) - keeps float4 alignment, breaks bank patterns
#define KP 65   // K-transposed pitch
#define ATT_SMEM (3 * 64 * QP * 4)   // Qs + (Kt/Ps shared) + Vs, bytes

__global__ __launch_bounds__(256)
void attn_kernel(const float* __restrict__ Qg, const float* __restrict__ Kg,
                 const float* __restrict__ Vg, float* __restrict__ Og)
{
    extern __shared__ float sm[];
    float* Qs  = sm;                 // [64][QP]
    float* KtP = sm + 64 * QP;       // K transposed [64 d][KP] ; reused as P [64][QP]
    float* Vs  = sm + 2 * 64 * QP;   // [64][QP]

    const int q0 = blockIdx.x * 64;
    const int h  = blockIdx.y;
    const int b  = blockIdx.z;
    const int tid = threadIdx.x;
    const int tr = tid >> 4;            // row group 0..15
    const int tc = tid & 15;            // col group 0..15
    const int rbase = tr * 4;
    const int cbase = tc * 4;
    const float scale = 0.125f;         // 1/sqrt(64)

    // load Q tile (scaled)
    for (int i = tid; i < 64 * 16; i += 256) {
        int r  = i >> 4;
        int cv = (i & 15) * 4;
        float4 v = *(const float4*)&Qg[((size_t)(b * TSEQ + q0 + r)) * DMODEL + h * DHEAD + cv];
        float* d = &Qs[r * QP + cv];
        d[0] = v.x * scale; d[1] = v.y * scale; d[2] = v.z * scale; d[3] = v.w * scale;
    }

    float m_[4], l_[4], o_[4][4];
#pragma unroll
    for (int i = 0; i < 4; i++) {
        m_[i] = -1e30f; l_[i] = 0.f;
#pragma unroll
        for (int j = 0; j < 4; j++) o_[i][j] = 0.f;
    }

    for (int j0 = 0; j0 <= q0; j0 += 64) {
        __syncthreads();   // protect Kt/Ps/Vs from previous iteration readers

        // load K (transposed into [d][key]) and V (natural [key][d])
        for (int i = tid; i < 64 * 16; i += 256) {
            int r  = i >> 4;
            int cv = (i & 15) * 4;
            size_t g = ((size_t)(b * TSEQ + j0 + r)) * DMODEL + h * DHEAD + cv;
            float4 kv = *(const float4*)&Kg[g];
            KtP[(cv + 0) * KP + r] = kv.x;
            KtP[(cv + 1) * KP + r] = kv.y;
            KtP[(cv + 2) * KP + r] = kv.z;
            KtP[(cv + 3) * KP + r] = kv.w;
            float4 vv = *(const float4*)&Vg[g];
            *(float4*)&Vs[r * QP + cv] = vv;
        }
        __syncthreads();

        // S = Q K^T (scaled)
        float s[4][4];
#pragma unroll
        for (int i = 0; i < 4; i++)
#pragma unroll
            for (int j = 0; j < 4; j++) s[i][j] = 0.f;

#pragma unroll 8
        for (int kk = 0; kk < 64; kk++) {
            float a0 = Qs[(rbase + 0) * QP + kk];
            float a1 = Qs[(rbase + 1) * QP + kk];
            float a2 = Qs[(rbase + 2) * QP + kk];
            float a3 = Qs[(rbase + 3) * QP + kk];
            float b0 = KtP[kk * KP + cbase + 0];
            float b1 = KtP[kk * KP + cbase + 1];
            float b2 = KtP[kk * KP + cbase + 2];
            float b3 = KtP[kk * KP + cbase + 3];
            s[0][0] += a0 * b0; s[0][1] += a0 * b1; s[0][2] += a0 * b2; s[0][3] += a0 * b3;
            s[1][0] += a1 * b0; s[1][1] += a1 * b1; s[1][2] += a1 * b2; s[1][3] += a1 * b3;
            s[2][0] += a2 * b0; s[2][1] += a2 * b1; s[2][2] += a2 * b2; s[2][3] += a2 * b3;
            s[3][0] += a3 * b0; s[3][1] += a3 * b1; s[3][2] += a3 * b2; s[3][3] += a3 * b3;
        }

        // causal mask (only needed on the diagonal chunk)
        if (j0 == q0) {
#pragma unroll
            for (int i = 0; i < 4; i++)
#pragma unroll
                for (int j = 0; j < 4; j++)
                    if (j0 + cbase + j > q0 + rbase + i) s[i][j] = -1e30f;
        }

        // streaming softmax update (row groups of 16 lanes: same tr)
#pragma unroll
        for (int i = 0; i < 4; i++) {
            float cm = fmaxf(fmaxf(s[i][0], s[i][1]), fmaxf(s[i][2], s[i][3]));
#pragma unroll
            for (int off = 8; off; off >>= 1)
                cm = fmaxf(cm, __shfl_xor_sync(0xffffffffu, cm, off));
            float mn = fmaxf(m_[i], cm);
            float corr = __expf(m_[i] - mn);
            m_[i] = mn;
            float rs = 0.f;
#pragma unroll
            for (int j = 0; j < 4; j++) {
                float p = __expf(s[i][j] - mn);
                s[i][j] = p;
                rs += p;
            }
#pragma unroll
            for (int off = 8; off; off >>= 1)
                rs += __shfl_xor_sync(0xffffffffu, rs, off);
            l_[i] = l_[i] * corr + rs;
#pragma unroll
            for (int j = 0; j < 4; j++) o_[i][j] *= corr;
        }

        __syncthreads();   // everyone is done reading KtP as K
        // write P into the KtP buffer (now used as Ps[64][QP])
#pragma unroll
        for (int i = 0; i < 4; i++) {
            float4 p4 = make_float4(s[i][0], s[i][1], s[i][2], s[i][3]);
            *(float4*)&KtP[(rbase + i) * QP + cbase] = p4;
        }
        __syncthreads();

        // O += P @ V
#pragma unroll 8
        for (int kk = 0; kk < 64; kk++) {
            float p0 = KtP[(rbase + 0) * QP + kk];
            float p1 = KtP[(rbase + 1) * QP + kk];
            float p2 = KtP[(rbase + 2) * QP + kk];
            float p3 = KtP[(rbase + 3) * QP + kk];
            float4 v4 = *(const float4*)&Vs[kk * QP + cbase];
            o_[0][0] += p0 * v4.x; o_[0][1] += p0 * v4.y; o_[0][2] += p0 * v4.z; o_[0][3] += p0 * v4.w;
            o_[1][0] += p1 * v4.x; o_[1][1] += p1 * v4.y; o_[1][2] += p1 * v4.z; o_[1][3] += p1 * v4.w;
            o_[2][0] += p2 * v4.x; o_[2][1] += p2 * v4.y; o_[2][2] += p2 * v4.z; o_[2][3] += p2 * v4.w;
            o_[3][0] += p3 * v4.x; o_[3][1] += p3 * v4.y; o_[3][2] += p3 * v4.z; o_[3][3] += p3 * v4.w;
        }
    }

    // final normalize + write (merge heads: [MTOK, 768])
#pragma unroll
    for (int i = 0; i < 4; i++) {
        float invl = 1.f / l_[i];
        int q = q0 + rbase + i;
        size_t base = ((size_t)(b * TSEQ + q)) * DMODEL + h * DHEAD + cbase;
        float4 o4 = make_float4(o_[i][0] * invl, o_[i][1] * invl,
                                o_[i][2] * invl, o_[i][3] * invl);
        *(float4*)&Og[base] = o4;
    }
}

// =================================================================
// LayerNorm over last dim (768). One block (256 threads) per row.
// =================================================================
__global__ __launch_bounds__(256)
void ln_kernel(const float* __restrict__ in, const float* __restrict__ g,
               const float* __restrict__ be, float* __restrict__ out)
{
    const int row = blockIdx.x;
    const int tid = threadIdx.x;
    const float* xr = in + (size_t)row * DMODEL;

    float v0 = xr[tid];
    float v1 = xr[tid + 256];
    float v2 = xr[tid + 512];
    float s  = v0 + v1 + v2;
    float s2 = v0 * v0 + v1 * v1 + v2 * v2;

    __shared__ float rs[8], rs2[8], stats[2];
#pragma unroll
    for (int off = 16; off; off >>= 1) {
        s  += __shfl_xor_sync(0xffffffffu, s,  off);
        s2 += __shfl_xor_sync(0xffffffffu, s2, off);
    }
    int w = tid >> 5, lane = tid & 31;
    if (lane == 0) { rs[w] = s; rs2[w] = s2; }
    __syncthreads();
    if (tid == 0) {
        float S = 0.f, S2 = 0.f;
#pragma unroll
        for (int i = 0; i < 8; i++) { S += rs[i]; S2 += rs2[i]; }
        float mean = S * (1.f / DMODEL);
        float var  = S2 * (1.f / DMODEL) - mean * mean;
        stats[0] = mean;
        stats[1] = rsqrtf(var + 1e-5f);
    }
    __syncthreads();
    float mean = stats[0], r = stats[1];
    float* orow = out + (size_t)row * DMODEL;
    orow[tid]       = (v0 - mean) * r * g[tid]       + be[tid];
    orow[tid + 256] = (v1 - mean) * r * g[tid + 256] + be[tid + 256];
    orow[tid + 512] = (v2 - mean) * r * g[tid + 512] + be[tid + 512];
}

// =================================================================
// Host launch
// =================================================================
extern "C" void kernel_launch(void* const* d_in, const int* in_sizes, int n_in,
                              void* d_out, int out_size)
{
    const float* x  = (const float*)d_in[0];
    const float* wq = (const float*)d_in[1];
    const float* bq = (const float*)d_in[2];
    const float* wk = (const float*)d_in[3];
    const float* bk = (const float*)d_in[4];
    const float* wv = (const float*)d_in[5];
    const float* bv = (const float*)d_in[6];
    const float* wo = (const float*)d_in[7];
    const float* bo = (const float*)d_in[8];
    const float* w1 = (const float*)d_in[9];
    const float* b1 = (const float*)d_in[10];
    const float* w2 = (const float*)d_in[11];
    const float* b2 = (const float*)d_in[12];
    const float* g1 = (const float*)d_in[13];
    const float* be1= (const float*)d_in[14];
    const float* g2 = (const float*)d_in[15];
    const float* be2= (const float*)d_in[16];
    float* out = (float*)d_out;

    float *Q, *K, *V, *ATT, *R1, *H, *FF, *R2;
    cudaGetSymbolAddress((void**)&Q,   g_Q);
    cudaGetSymbolAddress((void**)&K,   g_K);
    cudaGetSymbolAddress((void**)&V,   g_V);
    cudaGetSymbolAddress((void**)&ATT, g_ATT);
    cudaGetSymbolAddress((void**)&R1,  g_R1);
    cudaGetSymbolAddress((void**)&H,   g_H);
    cudaGetSymbolAddress((void**)&FF,  g_FF);
    cudaGetSymbolAddress((void**)&R2,  g_R2);

    cudaFuncSetAttribute(attn_kernel, cudaFuncAttributeMaxDynamicSharedMemorySize, ATT_SMEM);

    dim3 gD(DMODEL / 128, MTOK / 128);   // (6, 64)
    dim3 gF(DFF / 128,    MTOK / 128);   // (24, 64)

    // QKV projections
    gemm_kernel<<<gD, 256>>>(x, wq, bq, nullptr, Q, MTOK, DMODEL, DMODEL, 0);
    gemm_kernel<<<gD, 256>>>(x, wk, bk, nullptr, K, MTOK, DMODEL, DMODEL, 0);
    gemm_kernel<<<gD, 256>>>(x, wv, bv, nullptr, V, MTOK, DMODEL, DMODEL, 0);

    // causal flash attention
    attn_kernel<<<dim3(TSEQ / 64, NHEADS, BBATCH), 256, ATT_SMEM>>>(Q, K, V, ATT);

    // output projection + residual, LN1
    gemm_kernel<<<gD, 256>>>(ATT, wo, bo, x, R1, MTOK, DMODEL, DMODEL, 0);
    ln_kernel<<<MTOK, 256>>>(R1, g1, be1, H);

    // FFN
    gemm_kernel<<<gF, 256>>>(H, w1, b1, nullptr, FF, MTOK, DFF, DMODEL, 1);
    gemm_kernel<<<gD, 256>>>(FF, w2, b2, H, R2, MTOK, DMODEL, DFF, 0);

    // LN2 -> output
    ln_kernel<<<MTOK, 256>>>(R2, g2, be2, out);
}